// round 11
// baseline (speedup 1.0000x reference)
#include <cuda_runtime.h>
#include <cstdint>

#define ORD   24
#define TLEN  168
#define DD    512
#define SS    336
#define BB    256
#define KP    32            // padded K: 24 coefs + bias col + 7 zero cols
#define SROW  36            // smem row stride in floats (conflict-free frag LDS)

// Coefficient tables (3xTF32 hi/lo split), built by kernel A.
__device__ __align__(16) float g_Bhi[TLEN * KP];
__device__ __align__(16) float g_Blo[TLEN * KP];

// ---------------------------------------------------------------------------
__device__ __forceinline__ uint32_t to_tf32(float v) {
    uint32_t u;
    asm("cvt.rna.tf32.f32 %0, %1;" : "=r"(u) : "f"(v));
    return u;
}

// m16n8k8 tf32 MMA (sm_80+ base feature; valid on compute_103).
__device__ __forceinline__ void mma8(float& d0, float& d1, float& d2, float& d3,
                                     uint32_t a0, uint32_t a1, uint32_t a2,
                                     uint32_t a3, uint32_t b0, uint32_t b1) {
    asm volatile(
        "mma.sync.aligned.m16n8k8.row.col.f32.tf32.tf32.f32 "
        "{%0,%1,%2,%3}, {%4,%5,%6,%7}, {%8,%9}, {%0,%1,%2,%3};"
        : "+f"(d0), "+f"(d1), "+f"(d2), "+f"(d3)
        : "r"(a0), "r"(a1), "r"(a2), "r"(a3), "r"(b0), "r"(b1));
}

// ---------------------------------------------------------------------------
// Kernel A: coefficient recurrence in exact fp32; emit 3xTF32 hi/lo tables.
// Thread j owns coefficient column j (j==24: bias column; j>=25: zero pad).
// ---------------------------------------------------------------------------
__global__ void ar_coef_kernel(const float* __restrict__ W,
                               const float* __restrict__ bptr) {
    const int j = threadIdx.x;
    if (j >= KP) return;

    if (j >= 25) {
        for (int t = 0; t < TLEN; t++) {
            g_Bhi[t * KP + j] = 0.0f;
            g_Blo[t * KP + j] = 0.0f;
        }
        return;
    }

    float w[ORD];
#pragma unroll
    for (int i = 0; i < ORD; i++) w[i] = W[i];
    const float bias = bptr[0];

    float m[ORD];
#pragma unroll
    for (int i = 0; i < ORD; i++) m[i] = (j < ORD && i == j) ? 1.0f : 0.0f;

    for (int t = 0; t < TLEN; t++) {
        // tree over slots 0..22, single dependent FMA on the freshest slot 23
        float p[24];
#pragma unroll
        for (int i = 0; i < 23; i++) p[i] = w[i] * m[i];
        p[23] = 0.0f;
#pragma unroll
        for (int k = 0; k < 12; k++) p[k] = p[2 * k] + p[2 * k + 1];
#pragma unroll
        for (int k = 0; k < 6; k++)  p[k] = p[2 * k] + p[2 * k + 1];
#pragma unroll
        for (int k = 0; k < 3; k++)  p[k] = p[2 * k] + p[2 * k + 1];
        float y = (p[0] + p[1]) + p[2];
        y = fmaf(w[23], m[23], y);
        if (j == 24) y += bias;

        const float hi = __uint_as_float(to_tf32(y));
        const float lo = __uint_as_float(to_tf32(y - hi));
        g_Bhi[t * KP + j] = hi;
        g_Blo[t * KP + j] = lo;

#pragma unroll
        for (int i = 0; i < ORD - 1; i++) m[i] = m[i + 1];
        m[ORD - 1] = y;                 // recurrence stays full fp32
    }
}

// ---------------------------------------------------------------------------
// Kernel B: one CTA per (batch, d-quarter).
//   D[d=128][t=168] = A[d][k=32] * B[k][t],  A = [ctx | 1 | 0pad], B = coefs.
//   3xTF32: D = Ah*Bh + Ah*Bl + Al*Bh  (~fp32 accuracy).
//   4 warps; warp w owns d rows [32w, 32w+32) (2 m16-tiles) x 21 n8-tiles.
// ---------------------------------------------------------------------------
__global__ void __launch_bounds__(128)
ar_mma_kernel(const float* __restrict__ x, float* __restrict__ out) {
    extern __shared__ float s[];
    float* sAh = s;                         // [128][SROW]
    float* sAl = sAh + 128 * SROW;          // [128][SROW]
    float* sBh = sAl + 128 * SROW;          // [168][SROW]
    float* sBl = sBh + TLEN * SROW;         // [168][SROW]

    const int tid   = threadIdx.x;
    const int warp  = tid >> 5;
    const int lane  = tid & 31;
    const int g     = lane >> 2;            // groupID 0..7
    const int tg    = lane & 3;             // thread-in-group 0..3
    const int batch = blockIdx.x >> 2;
    const int dq    = blockIdx.x & 3;

    // ---- stage B tables: [168][32] global -> [168][36] smem, float4 ----
    for (int v = tid; v < TLEN * 8; v += 128) {
        const int row = v >> 3, c4 = v & 7;
        *reinterpret_cast<float4*>(&sBh[row * SROW + c4 * 4]) =
            reinterpret_cast<const float4*>(g_Bhi)[v];
        *reinterpret_cast<float4*>(&sBl[row * SROW + c4 * 4]) =
            reinterpret_cast<const float4*>(g_Blo)[v];
    }

    // ---- stage A: thread d=tid, hi/lo split of ctx ----
    {
        const float* xb =
            x + ((size_t)batch * SS + (SS - ORD)) * DD + dq * 128 + tid;
#pragma unroll
        for (int k = 0; k < ORD; k++) {
            const float v  = xb[(size_t)k * DD];       // coalesced
            const float hi = __uint_as_float(to_tf32(v));
            sAh[tid * SROW + k] = hi;
            sAl[tid * SROW + k] = __uint_as_float(to_tf32(v - hi));
        }
        sAh[tid * SROW + 24] = 1.0f;                   // bias column
        sAl[tid * SROW + 24] = 0.0f;
#pragma unroll
        for (int k = 25; k < KP; k++) {
            sAh[tid * SROW + k] = 0.0f;
            sAl[tid * SROW + k] = 0.0f;
        }
    }
    __syncthreads();

    // ---- A fragments (resident for the whole tile): [2 m][4 kc][4 regs] ----
    uint32_t ah[2][4][4], al[2][4][4];
    const int m0 = warp * 32;
#pragma unroll
    for (int mi = 0; mi < 2; mi++) {
        const int r = m0 + mi * 16;
#pragma unroll
        for (int kc = 0; kc < 4; kc++) {
            const int k0 = kc * 8;
            ah[mi][kc][0] = __float_as_uint(sAh[(r + g) * SROW + k0 + tg]);
            ah[mi][kc][1] = __float_as_uint(sAh[(r + g + 8) * SROW + k0 + tg]);
            ah[mi][kc][2] = __float_as_uint(sAh[(r + g) * SROW + k0 + tg + 4]);
            ah[mi][kc][3] = __float_as_uint(sAh[(r + g + 8) * SROW + k0 + tg + 4]);
            al[mi][kc][0] = __float_as_uint(sAl[(r + g) * SROW + k0 + tg]);
            al[mi][kc][1] = __float_as_uint(sAl[(r + g + 8) * SROW + k0 + tg]);
            al[mi][kc][2] = __float_as_uint(sAl[(r + g) * SROW + k0 + tg + 4]);
            al[mi][kc][3] = __float_as_uint(sAl[(r + g + 8) * SROW + k0 + tg + 4]);
        }
    }

    float* ob = out + (size_t)batch * TLEN * DD + dq * 128 + m0;

    // ---- main loop over 21 n-tiles of 8 t ----
#pragma unroll 1
    for (int nt = 0; nt < 21; nt++) {
        const int t0 = nt * 8;

        // B fragments: b0 = B[k=kc*8+tg][n=t0+g], b1 = k+4  (sB is [t][k])
        uint32_t bh[4][2], bl[4][2];
#pragma unroll
        for (int kc = 0; kc < 4; kc++) {
            const int rb = (t0 + g) * SROW + kc * 8 + tg;
            bh[kc][0] = __float_as_uint(sBh[rb]);
            bh[kc][1] = __float_as_uint(sBh[rb + 4]);
            bl[kc][0] = __float_as_uint(sBl[rb]);
            bl[kc][1] = __float_as_uint(sBl[rb + 4]);
        }

        float acc0[4] = {0.f, 0.f, 0.f, 0.f};
        float acc1[4] = {0.f, 0.f, 0.f, 0.f};
#pragma unroll
        for (int kc = 0; kc < 4; kc++) {   // hi*hi
            mma8(acc0[0], acc0[1], acc0[2], acc0[3],
                 ah[0][kc][0], ah[0][kc][1], ah[0][kc][2], ah[0][kc][3],
                 bh[kc][0], bh[kc][1]);
            mma8(acc1[0], acc1[1], acc1[2], acc1[3],
                 ah[1][kc][0], ah[1][kc][1], ah[1][kc][2], ah[1][kc][3],
                 bh[kc][0], bh[kc][1]);
        }
#pragma unroll
        for (int kc = 0; kc < 4; kc++) {   // hi*lo
            mma8(acc0[0], acc0[1], acc0[2], acc0[3],
                 ah[0][kc][0], ah[0][kc][1], ah[0][kc][2], ah[0][kc][3],
                 bl[kc][0], bl[kc][1]);
            mma8(acc1[0], acc1[1], acc1[2], acc1[3],
                 ah[1][kc][0], ah[1][kc][1], ah[1][kc][2], ah[1][kc][3],
                 bl[kc][0], bl[kc][1]);
        }
#pragma unroll
        for (int kc = 0; kc < 4; kc++) {   // lo*hi
            mma8(acc0[0], acc0[1], acc0[2], acc0[3],
                 al[0][kc][0], al[0][kc][1], al[0][kc][2], al[0][kc][3],
                 bh[kc][0], bh[kc][1]);
            mma8(acc1[0], acc1[1], acc1[2], acc1[3],
                 al[1][kc][0], al[1][kc][1], al[1][kc][2], al[1][kc][3],
                 bh[kc][0], bh[kc][1]);
        }

        // stores: c0:(d=g, t=t0+2tg) c1:(t+1) c2:(d=g+8) c3:(d=g+8, t+1)
        {
            const size_t tq = (size_t)(t0 + tg * 2) * DD;
            __stcs(ob + tq + g,            acc0[0]);
            __stcs(ob + tq + DD + g,       acc0[1]);
            __stcs(ob + tq + g + 8,        acc0[2]);
            __stcs(ob + tq + DD + g + 8,   acc0[3]);
            __stcs(ob + tq + g + 16,       acc1[0]);
            __stcs(ob + tq + DD + g + 16,  acc1[1]);
            __stcs(ob + tq + g + 24,       acc1[2]);
            __stcs(ob + tq + DD + g + 24,  acc1[3]);
        }
    }
}

// ---------------------------------------------------------------------------
extern "C" void kernel_launch(void* const* d_in, const int* in_sizes, int n_in,
                              void* d_out, int out_size) {
    const float* x = (const float*)d_in[0];   // [256, 336, 512] f32
    const float* W = (const float*)d_in[1];   // [24, 1] f32
    const float* b = (const float*)d_in[2];   // [1] f32
    float* out = (float*)d_out;               // [256, 168, 512] f32

    const int smem = (2 * 128 * SROW + 2 * TLEN * SROW) * (int)sizeof(float);
    cudaFuncSetAttribute(ar_mma_kernel,
                         cudaFuncAttributeMaxDynamicSharedMemorySize, smem);

    ar_coef_kernel<<<1, 32>>>(W, b);
    ar_mma_kernel<<<BB * 4, 128, smem>>>(x, out);
}

// round 12
// speedup vs baseline: 1.4817x; 1.4817x over previous
#include <cuda_runtime.h>
#include <cstdint>

#define ORD   24
#define TLEN  168
#define DD    512
#define SS    336
#define BB    256
#define SROW  36            // smem B row stride in floats (conflict-free frags)
#define NTILE 1024          // tiles = batch x d-quarter
#define GRIDB 592           // 148 SMs x 4 resident CTAs, one persistent wave

__device__ int g_counter = 0;   // work-steal counter (self-resets per launch)
__device__ int g_done    = 0;

// ---------------------------------------------------------------------------
__device__ __forceinline__ uint32_t to_tf32(float v) {
    uint32_t u;
    asm("cvt.rna.tf32.f32 %0, %1;" : "=r"(u) : "f"(v));
    return u;
}

// m16n8k8 tf32 MMA (sm_80+ base feature; valid on compute_103).
__device__ __forceinline__ void mma8(float& d0, float& d1, float& d2, float& d3,
                                     uint32_t a0, uint32_t a1, uint32_t a2,
                                     uint32_t a3, uint32_t b0, uint32_t b1) {
    asm volatile(
        "mma.sync.aligned.m16n8k8.row.col.f32.tf32.tf32.f32 "
        "{%0,%1,%2,%3}, {%4,%5,%6,%7}, {%8,%9}, {%0,%1,%2,%3};"
        : "+f"(d0), "+f"(d1), "+f"(d2), "+f"(d3)
        : "r"(a0), "r"(a1), "r"(a2), "r"(a3), "r"(b0), "r"(b1));
}

// ---------------------------------------------------------------------------
// Fused persistent kernel.
//   Prologue: threads 0..24 run the exact-fp32 coef recurrence (thread j =
//   coefficient column j; j==24 = bias column) writing 3xTF32 hi/lo tables
//   into smem; threads 25+ zero-pad cols 25..31.
//   Mainloop: tile = (batch, d-quarter). Warp w owns d rows [32w,32w+32)
//   (2 m16-tiles) x 21 n8-tiles of t. A fragments (ctx hi/lo) come straight
//   from global; B fragments from smem. 3 passes with SEPARATE accumulators
//   (6 short independent HMMA chains): D = Ah*Bh + Ah*Bl + Al*Bh.
// ---------------------------------------------------------------------------
__global__ void __launch_bounds__(128, 4)
ar_fused_kernel(const float* __restrict__ x, const float* __restrict__ W,
                const float* __restrict__ bptr, float* __restrict__ out) {
    __shared__ float sBh[TLEN * SROW];   // 23.6 KB
    __shared__ float sBl[TLEN * SROW];   // 23.6 KB
    __shared__ int s_tile;

    const int tid  = threadIdx.x;
    const int warp = tid >> 5;
    const int lane = tid & 31;
    const int g    = lane >> 2;          // groupID 0..7
    const int tg   = lane & 3;           // thread-in-group 0..3

    // ---- coef prologue ----
    if (tid < 25) {
        const int j = tid;
        float w[ORD];
#pragma unroll
        for (int i = 0; i < ORD; i++) w[i] = W[i];
        const float bias = bptr[0];

        float m[ORD];
#pragma unroll
        for (int i = 0; i < ORD; i++) m[i] = (j < ORD && i == j) ? 1.0f : 0.0f;

        for (int t = 0; t < TLEN; t++) {
            float p[24];
#pragma unroll
            for (int i = 0; i < 23; i++) p[i] = w[i] * m[i];
            p[23] = 0.0f;
#pragma unroll
            for (int k = 0; k < 12; k++) p[k] = p[2 * k] + p[2 * k + 1];
#pragma unroll
            for (int k = 0; k < 6; k++)  p[k] = p[2 * k] + p[2 * k + 1];
#pragma unroll
            for (int k = 0; k < 3; k++)  p[k] = p[2 * k] + p[2 * k + 1];
            float y = (p[0] + p[1]) + p[2];
            y = fmaf(w[23], m[23], y);
            if (j == 24) y += bias;

            const float hi = __uint_as_float(to_tf32(y));
            sBh[t * SROW + j] = hi;
            sBl[t * SROW + j] = __uint_as_float(to_tf32(y - hi));

#pragma unroll
            for (int i = 0; i < ORD - 1; i++) m[i] = m[i + 1];
            m[ORD - 1] = y;              // recurrence stays full fp32
        }
    } else {
        // zero-pad cols 25..31 (fragment reads touch cols 0..31 only)
        for (int i = tid - 25; i < TLEN * 7; i += 103) {
            const int row = i / 7, col = 25 + i % 7;
            sBh[row * SROW + col] = 0.0f;
            sBl[row * SROW + col] = 0.0f;
        }
    }
    __syncthreads();

    int tile = blockIdx.x;               // first tile pre-assigned

    for (;;) {
        const int batch = tile >> 2, dq = tile & 3;
        const float* xb =
            x + ((size_t)batch * SS + (SS - ORD)) * DD + dq * 128;
        const int m0 = warp * 32;

        // ---- A fragments straight from global (one-time per tile) ----
        uint32_t ah[2][4][4], al[2][3][4];
#pragma unroll
        for (int mi = 0; mi < 2; mi++) {
            const int r0 = m0 + mi * 16 + g;
            const int r1 = r0 + 8;
#pragma unroll
            for (int kc = 0; kc < 3; kc++) {
                const int ka = kc * 8 + tg, kb = ka + 4;
                const float v0 = xb[(size_t)ka * DD + r0];
                const float v1 = xb[(size_t)ka * DD + r1];
                const float v2 = xb[(size_t)kb * DD + r0];
                const float v3 = xb[(size_t)kb * DD + r1];
                const uint32_t h0 = to_tf32(v0), h1 = to_tf32(v1);
                const uint32_t h2 = to_tf32(v2), h3 = to_tf32(v3);
                ah[mi][kc][0] = h0;
                ah[mi][kc][1] = h1;
                ah[mi][kc][2] = h2;
                ah[mi][kc][3] = h3;
                al[mi][kc][0] = to_tf32(v0 - __uint_as_float(h0));
                al[mi][kc][1] = to_tf32(v1 - __uint_as_float(h1));
                al[mi][kc][2] = to_tf32(v2 - __uint_as_float(h2));
                al[mi][kc][3] = to_tf32(v3 - __uint_as_float(h3));
            }
            // kc=3: k=24+tg -> bias column (1.0 at tg==0); k=28+tg -> 0
            const uint32_t one = (tg == 0) ? __float_as_uint(1.0f) : 0u;
            ah[mi][3][0] = one;
            ah[mi][3][1] = one;
            ah[mi][3][2] = 0u;
            ah[mi][3][3] = 0u;
        }

        float* ob = out + (size_t)batch * TLEN * DD + dq * 128 + m0;

        // ---- 21 n-tiles of 8 t ----
#pragma unroll 1
        for (int nt = 0; nt < 21; nt++) {
            const int t0 = nt * 8;

            uint32_t bh[4][2], bl[4][2];
#pragma unroll
            for (int kc = 0; kc < 4; kc++) {
                const int rb = (t0 + g) * SROW + kc * 8 + tg;
                bh[kc][0] = __float_as_uint(sBh[rb]);
                bh[kc][1] = __float_as_uint(sBh[rb + 4]);
                bl[kc][0] = __float_as_uint(sBl[rb]);
                bl[kc][1] = __float_as_uint(sBl[rb + 4]);
            }

            // 6 independent accumulator chains (<=4 MMAs deep each)
            float aH0[4] = {0, 0, 0, 0}, aM0[4] = {0, 0, 0, 0},
                  aL0[4] = {0, 0, 0, 0};
            float aH1[4] = {0, 0, 0, 0}, aM1[4] = {0, 0, 0, 0},
                  aL1[4] = {0, 0, 0, 0};
#pragma unroll
            for (int kc = 0; kc < 4; kc++) {   // hi*hi
                mma8(aH0[0], aH0[1], aH0[2], aH0[3],
                     ah[0][kc][0], ah[0][kc][1], ah[0][kc][2], ah[0][kc][3],
                     bh[kc][0], bh[kc][1]);
                mma8(aH1[0], aH1[1], aH1[2], aH1[3],
                     ah[1][kc][0], ah[1][kc][1], ah[1][kc][2], ah[1][kc][3],
                     bh[kc][0], bh[kc][1]);
            }
#pragma unroll
            for (int kc = 0; kc < 4; kc++) {   // hi*lo
                mma8(aM0[0], aM0[1], aM0[2], aM0[3],
                     ah[0][kc][0], ah[0][kc][1], ah[0][kc][2], ah[0][kc][3],
                     bl[kc][0], bl[kc][1]);
                mma8(aM1[0], aM1[1], aM1[2], aM1[3],
                     ah[1][kc][0], ah[1][kc][1], ah[1][kc][2], ah[1][kc][3],
                     bl[kc][0], bl[kc][1]);
            }
#pragma unroll
            for (int kc = 0; kc < 3; kc++) {   // lo*hi (kc=3 is all-zero A-lo)
                mma8(aL0[0], aL0[1], aL0[2], aL0[3],
                     al[0][kc][0], al[0][kc][1], al[0][kc][2], al[0][kc][3],
                     bh[kc][0], bh[kc][1]);
                mma8(aL1[0], aL1[1], aL1[2], aL1[3],
                     al[1][kc][0], al[1][kc][1], al[1][kc][2], al[1][kc][3],
                     bh[kc][0], bh[kc][1]);
            }

            // stores (mapping identical to the round-11 validated kernel)
            const size_t tq = (size_t)(t0 + tg * 2) * DD;
            __stcs(ob + tq + g,           (aH0[0] + aM0[0]) + aL0[0]);
            __stcs(ob + tq + DD + g,      (aH0[1] + aM0[1]) + aL0[1]);
            __stcs(ob + tq + g + 8,       (aH0[2] + aM0[2]) + aL0[2]);
            __stcs(ob + tq + DD + g + 8,  (aH0[3] + aM0[3]) + aL0[3]);
            __stcs(ob + tq + g + 16,      (aH1[0] + aM1[0]) + aL1[0]);
            __stcs(ob + tq + DD + g + 16, (aH1[1] + aM1[1]) + aL1[1]);
            __stcs(ob + tq + g + 24,      (aH1[2] + aM1[2]) + aL1[2]);
            __stcs(ob + tq + DD + g + 24, (aH1[3] + aM1[3]) + aL1[3]);
        }

        // ---- steal next tile ----
        __syncthreads();
        if (tid == 0) s_tile = GRIDB + atomicAdd(&g_counter, 1);
        __syncthreads();
        tile = s_tile;
        if (tile >= NTILE) break;
    }

    // ---- self-reset counters so each graph replay is identical ----
    if (tid == 0) {
        const int d = atomicAdd(&g_done, 1);
        if (d == GRIDB - 1) {
            atomicExch(&g_counter, 0);
            atomicExch(&g_done, 0);
        }
    }
}

// ---------------------------------------------------------------------------
extern "C" void kernel_launch(void* const* d_in, const int* in_sizes, int n_in,
                              void* d_out, int out_size) {
    const float* x = (const float*)d_in[0];   // [256, 336, 512] f32
    const float* W = (const float*)d_in[1];   // [24, 1] f32
    const float* b = (const float*)d_in[2];   // [1] f32
    float* out = (float*)d_out;               // [256, 168, 512] f32

    ar_fused_kernel<<<GRIDB, 128>>>(x, W, b, out);
}